// round 6
// baseline (speedup 1.0000x reference)
#include <cuda_runtime.h>
#include <cuda_bf16.h>
#include <cstdint>

#define T_LEN  4000
#define HALF   2000
#define BLOCK  128
#define SEG    16
#define NSEG   125
#define GRID   1024
// pad 4 floats per 32: 16B-aligned, conflict-free for LDS.128 patterns used here
#define P16(i) ((i) + (((i) >> 5) << 2))
#define BUFSZ  2248   // P16(1999)+1

__device__ __forceinline__ float fast_exp2(float x) {
    float y; asm("ex2.approx.ftz.f32 %0, %1;" : "=f"(y) : "f"(x)); return y;
}
__device__ __forceinline__ float fast_log2(float x) {
    float y; asm("lg2.approx.ftz.f32 %0, %1;" : "=f"(y) : "f"(x)); return y;
}
__device__ __forceinline__ float fast_sqrt(float x) {
    float y; asm("sqrt.approx.ftz.f32 %0, %1;" : "=f"(y) : "f"(x)); return y;
}
__device__ __forceinline__ void cp_async16(uint32_t dst, const float* src) {
    asm volatile("cp.async.cg.shared.global [%0], [%1], 16;\n" :: "r"(dst), "l"(src));
}
#define CP_COMMIT() asm volatile("cp.async.commit_group;\n" ::: "memory")
#define CP_WAIT1()  asm volatile("cp.async.wait_group 1;\n" ::: "memory")

__constant__ float c_S   = 512.0f / 1323.0f;   // HOP/(SR*INIT_T), exact
__constant__ float c_OMS = 1.0f - 512.0f / 1323.0f;

struct Params { float delta, r, dr, nalpha; bool rhalf; };

__device__ __forceinline__ float pcen_elem(float xv, float M, const Params& p) {
    float L    = fast_log2(1e-6f + M);
    float sinv = fast_exp2(p.nalpha * L);
    float bse  = fmaf(xv, sinv, p.delta);            // > 0
    return (p.rhalf ? fast_sqrt(bse)
                    : fast_exp2(p.r * fast_log2(bse))) - p.dr;
}

// Horner over 4 taps: M <- recurrence advanced by v.x..v.w
__device__ __forceinline__ float horner4(float M, float4 v, float S, float OMS) {
    M = OMS * M + S * v.x;
    M = OMS * M + S * v.y;
    M = OMS * M + S * v.z;
    M = OMS * M + S * v.w;
    return M;
}

__global__ __launch_bounds__(BLOCK) void pcen_kernel(
    const float* __restrict__ x,
    const float* __restrict__ alpha_p,
    const float* __restrict__ delta_p,
    const float* __restrict__ r_p,
    float* __restrict__ out,
    int rows)
{
    __shared__ __align__(16) float bufs[2][BUFSZ];
    __shared__ __align__(16) float scratch[32];     // raw x[1968..1999] of current row

    const int bid = blockIdx.x;
    const int tid = threadIdx.x;

    int nrows = 0;
    if (bid < rows) nrows = (rows - 1 - bid) / GRID + 1;
    const int nunits = 2 * nrows;
    if (nunits == 0) return;

    uint32_t sbase[2];
    sbase[0] = (uint32_t)__cvta_generic_to_shared(bufs[0]);
    sbase[1] = (uint32_t)__cvta_generic_to_shared(bufs[1]);

    // scalar params
    Params p;
    {
        float alpha = fminf(fmaxf(alpha_p[0], 0.01f), 0.99f);
        p.delta  = fabsf(delta_p[0]) + 1e-6f;
        p.r      = fminf(fmaxf(r_p[0], 0.01f), 1.0f);
        p.rhalf  = (p.r == 0.5f);
        p.dr     = p.rhalf ? fast_sqrt(p.delta)
                           : fast_exp2(p.r * fast_log2(p.delta));
        p.nalpha = -alpha;
    }
    const float S   = c_S;
    const float OMS = c_OMS;

    const bool act = tid < NSEG;
    const int  t0l = SEG * tid;

    // prefetch unit 0
    {
        const float* src = x + (size_t)bid * T_LEN;
        uint32_t dst = sbase[0];
        #pragma unroll
        for (int m = tid; m < 500; m += BLOCK)
            cp_async16(dst + 16u * m + 16u * (m >> 3), src + 4 * m);
    }
    CP_COMMIT();

    #pragma unroll 1
    for (int n = 0; n < nunits; n++) {
        const int  half = n & 1;
        const int  row  = bid + (n >> 1) * GRID;
        float* __restrict__ buf = bufs[half];

        // prefetch next unit into the other buffer
        if (n + 1 < nunits) {
            const int nh  = (n + 1) & 1;
            const int nr  = bid + ((n + 1) >> 1) * GRID;
            const float* src = x + (size_t)nr * T_LEN + nh * HALF;
            uint32_t dst = sbase[nh];
            #pragma unroll
            for (int m = tid; m < 500; m += BLOCK)
                cp_async16(dst + 16u * m + 16u * (m >> 3), src + 4 * m);
        }
        CP_COMMIT();
        CP_WAIT1();                    // unit n staged (n+1 may still fly)
        __syncthreads();               // BAR1: data visible to all

        // save raw tail of half0 for half1's boundary windows (consumed next unit)
        if (half == 0 && tid < 32)
            scratch[tid] = buf[P16(1968 + tid)];

        // ---- window: Horner estimate of M[t0-1] (or exact at row start) ----
        float M = 0.0f;
        if (act) {
            if (tid >= 2) {
                const int b = t0l - 32;
                #pragma unroll
                for (int g = 0; g < 8; g++) {
                    float4 v = *(const float4*)&buf[P16(b + 4 * g)];
                    M = horner4(M, v, S, OMS);
                }
            } else if (half == 0) {
                if (tid == 0) {
                    M = buf[P16(0)];           // M[-1] seed s.t. step gives M[0]=x[0]
                } else {
                    // exact M[15]: seed x[0], taps x[1..15]
                    float4 v0 = *(const float4*)&buf[P16(0)];
                    M = v0.x;
                    M = OMS * M + S * v0.y;
                    M = OMS * M + S * v0.z;
                    M = OMS * M + S * v0.w;
                    #pragma unroll
                    for (int g = 1; g < 4; g++) {
                        float4 v = *(const float4*)&buf[P16(4 * g)];
                        M = horner4(M, v, S, OMS);
                    }
                }
            } else {
                if (tid == 0) {
                    #pragma unroll
                    for (int g = 0; g < 8; g++) {
                        float4 v = *(const float4*)&scratch[4 * g];
                        M = horner4(M, v, S, OMS);
                    }
                } else {
                    #pragma unroll
                    for (int g = 4; g < 8; g++) {
                        float4 v = *(const float4*)&scratch[4 * g];
                        M = horner4(M, v, S, OMS);
                    }
                    #pragma unroll
                    for (int g = 0; g < 4; g++) {
                        float4 v = *(const float4*)&buf[P16(4 * g)];
                        M = horner4(M, v, S, OMS);
                    }
                }
            }
        }
        __syncthreads();               // BAR2: window reads + tail save done

        // ---- compute 16 elems in-place (uniform recurrence from M[t0-1]) ----
        if (act) {
            #pragma unroll
            for (int q = 0; q < 4; q++) {
                float4 v = *(const float4*)&buf[P16(t0l + 4 * q)];
                float4 o;
                M = OMS * M + S * v.x;  o.x = pcen_elem(v.x, M, p);
                M = OMS * M + S * v.y;  o.y = pcen_elem(v.y, M, p);
                M = OMS * M + S * v.z;  o.z = pcen_elem(v.z, M, p);
                M = OMS * M + S * v.w;  o.w = pcen_elem(v.w, M, p);
                *(float4*)&buf[P16(t0l + 4 * q)] = o;
            }
        }
        __syncthreads();               // BAR3: results ready

        // ---- coalesced writeback ----
        {
            float* __restrict__ outr = out + (size_t)row * T_LEN + half * HALF;
            #pragma unroll
            for (int i = tid; i < 500; i += BLOCK) {
                float4 v = *(const float4*)&buf[P16(4 * i)];
                *(float4*)(outr + 4 * i) = v;
            }
        }
        __syncthreads();               // BAR4: buffer free for prefetch n+2
    }
}

extern "C" void kernel_launch(void* const* d_in, const int* in_sizes, int n_in,
                              void* d_out, int out_size) {
    const float* mel   = (const float*)d_in[0];
    const float* alpha = (const float*)d_in[1];
    const float* delta = (const float*)d_in[2];
    const float* r     = (const float*)d_in[3];
    float* out = (float*)d_out;

    int rows = out_size / T_LEN;   // 16384
    pcen_kernel<<<GRID, BLOCK>>>(mel, alpha, delta, r, out, rows);
}